// round 11
// baseline (speedup 1.0000x reference)
#include <cuda_runtime.h>

// Problem constants (fixed by the reference setup)
#define DE   200          // entity / output dim
#define DR   200          // relation dim
#define DIN  400          // DE + DR
#define NB   4            // num bases
#define KTOT (NB * DIN)   // 1600 rows of the collapsed matvec

#define NBLK 148          // one wave
#define NTHR 512
#define NMM  50           // consumer blocks: each owns 4 output columns
#define OPB  4            // outputs per consumer block (50*4 = 200 exact)
#define NJ   13           // basis regs per thread (13*128 = 1664 >= 1600)
#define MAXM 1024         // slot capacity (expected ~8 matches)
#define NSPEC 16          // slots consumed speculatively (one per warp)

// persistent scratch (static device globals — no allocation).
// g_arrive: low16 = block arrivals, high16 = match count / slot allocator.
//           Reset to 0 by the releaser every launch.
// g_rel:    low32 = monotonically increasing launch sequence, high32 = count.
// g_slot:   bits[48:64) = launch seq tag (stale slots auto-invalid),
//           bits[18:35) = nid, [9:18) = ri, [0:9) = ty.
__device__ unsigned           g_arrive;
__device__ unsigned long long g_rel;
__device__ unsigned long long g_slot[MAXM];

__global__ void __launch_bounds__(NTHR, 1)
fused_kernel(const float* __restrict__ ent,
             const float* __restrict__ relemb,
             const float* __restrict__ basis,
             const float* __restrict__ att,
             const int*   __restrict__ node_id,
             const int*   __restrict__ edge_src,
             const int*   __restrict__ edge_dst,
             const int*   __restrict__ edge_type,
             const int*   __restrict__ rel_index,
             const int*   __restrict__ u_ptr,
             float* __restrict__ out,
             int E) {
    const int tid    = threadIdx.x;
    const int wid    = tid >> 5;
    const int lane   = tid & 31;
    const bool is_mv = (blockIdx.x < NMM);

    __shared__ float sy[KTOT];      // y vector (6.4 kB)
    __shared__ float s_part[16];    // per-warp partials for the final reduce
    __shared__ int   s_cnt;

    // Launch sequence: plain (L1-cached) load, one L2 touch per SM.
    const unsigned seq_old = (unsigned)g_rel;
    const unsigned seq16   = (seq_old + 1u) & 0xFFFFu;

    // Consumer prefetch: basis column chunk into registers (overlaps scan).
    // Thread handles output o = blockIdx*4 + (tid>>7), k = (tid&127) + 128*j.
    const int o    = blockIdx.x * OPB + (tid >> 7);
    const int krow = tid & 127;
    float breg[NJ];
    if (is_mv) {
        #pragma unroll
        for (int j = 0; j < NJ; j++) {
            int k = krow + 128 * j;
            breg[j] = (k < KTOT) ? __ldcg(&basis[(size_t)k * DE + o]) : 0.0f;
        }
        // zero y
        #pragma unroll
        for (int j = 0; j < 4; j++) {
            int k = tid + NTHR * j;
            if (k < KTOT) sy[k] = 0.0f;
        }
    }
    __syncthreads();                // sy visible before speculative adds

    // ── Phase 1: scan edge_dst (all 148 blocks). A finder allocates its slot
    //    from the SAME atomic counter the barrier uses (high16), resolves the
    //    pointer chain, and publishes ONE seq-tagged 64-bit word. ──
    auto found = [&](int e) {
        unsigned old = atomicAdd(&g_arrive, 1u << 16);
        unsigned p = old >> 16;
        if (p < MAXM) {
            int s  = __ldcg(&edge_src[e]);   // these three issue in parallel
            int ri = __ldcg(&rel_index[e]);
            int ty = __ldcg(&edge_type[e]);
            int nid = __ldcg(&node_id[s]);   // the only serial dependency
            *(volatile unsigned long long*)&g_slot[p] =
                  ((unsigned long long)seq16 << 48)
                | ((unsigned long long)(unsigned)nid << 18)
                | ((unsigned long long)(unsigned)ri  << 9)
                |  (unsigned long long)(unsigned)ty;
        }
    };
    {
        const int u  = *u_ptr;               // L1-cached broadcast
        const int gt = blockIdx.x * NTHR + tid;
        const int GT = NBLK * NTHR;
        const int nv = E >> 2;
        const int4* ed4 = (const int4*)edge_dst;
        for (int i = gt; i < nv; i += 2 * GT) {       // 2-wide MLP
            int  i2 = i + GT;
            bool h2 = i2 < nv;
            int4 v1 = __ldcg(&ed4[i]);
            int4 v2;
            if (h2) v2 = __ldcg(&ed4[i2]);
            int b1 = i << 2;
            if (v1.x == u) found(b1 + 0);
            if (v1.y == u) found(b1 + 1);
            if (v1.z == u) found(b1 + 2);
            if (v1.w == u) found(b1 + 3);
            if (h2) {
                int b2 = i2 << 2;
                if (v2.x == u) found(b2 + 0);
                if (v2.y == u) found(b2 + 1);
                if (v2.z == u) found(b2 + 2);
                if (v2.w == u) found(b2 + 3);
            }
        }
        for (int e = (nv << 2) + gt; e < E; e += GT) {  // scalar tail
            if (__ldcg(&edge_dst[e]) == u) found(e);
        }
    }

    // ── Barrier arrival; the releaser's OWN atomic return carries the count. ──
    __syncthreads();
    if (tid == 0) {
        __threadfence();
        unsigned old = atomicAdd(&g_arrive, 1u);
        if ((old & 0xFFFFu) == NBLK - 1) {            // releaser
            unsigned cnt = old >> 16;
            g_arrive = 0;                             // reset for next launch
            __threadfence();
            atomicExch(&g_rel, ((unsigned long long)cnt << 32)
                               | (unsigned long long)(seq_old + 1u));
        }
    }

    if (!is_mv) return;                               // scan-only blocks done

    // helper: accumulate slot m's contribution to y (this warp sweeps all k)
    auto consume = [&](unsigned long long v) {
        int nid = (int)((v >> 18) & 0x1FFFF);
        int ri  = (int)((v >> 9) & 0x1FF);
        int ty  = (int)(v & 0x1FF);
        float4 a4 = *(const float4*)(att + (size_t)ty * NB);
        const float* aa = (const float*)&a4;
        #pragma unroll 5
        for (int j = 0; j < KTOT / 32; j++) {         // 50 iters, coalesced
            int k = lane + 32 * j;
            int b = k / DIN;
            int i = k - b * DIN;
            float x = (i < DE)
                ? __ldcg(&ent[(size_t)nid * DE + i])
                : __ldcg(&relemb[(size_t)ri * DR + (i - DE)]);
            atomicAdd(&sy[k], aa[b] * x);
        }
    };

    // ── Speculative consume (pre-release): warp w polls slot w and sweeps
    //    the full k-range for it the instant it is published. ──
    if (wid < NSPEC) {
        const int mm = wid;
        unsigned long long v;
        bool have = false;
        for (;;) {
            v = *(volatile unsigned long long*)&g_slot[mm];
            if ((unsigned)(v >> 48) == seq16) { have = true; break; }
            unsigned long long r = *(volatile unsigned long long*)&g_rel;
            if ((unsigned)r != seq_old) {             // released
                int cnt = (int)(r >> 32);
                if (mm >= cnt) break;                 // never fills
                __threadfence();                      // acquire
                v = *(volatile unsigned long long*)&g_slot[mm];
                have = ((unsigned)(v >> 48) == seq16);
                break;
            }
        }
        if (have) consume(v);
    }

    // ── Release wait (usually already satisfied) ──
    if (tid == 0) {
        unsigned long long r;
        do { r = *(volatile unsigned long long*)&g_rel; }
        while ((unsigned)r == seq_old);
        __threadfence();                              // acquire
        s_cnt = (int)(r >> 32);
    }
    __syncthreads();
    const int   cnt  = s_cnt;
    const int   cntc = cnt < MAXM ? cnt : MAXM;
    const float inv  = 1.0f / fmaxf((float)cnt, 1.0f);

    if (cntc > NSPEC) {                               // rare (expected cnt≈8)
        for (int m = NSPEC + wid; m < cntc; m += NSPEC) {
            consume(g_slot[m]);
        }
        __syncthreads();
    }
    __syncthreads();                                  // sy complete

    // ── Stage 2: out[o] = inv * sum_k y[k]*basis[k,o]; pure local reduce,
    //    final write is a plain STG (no REDG, no inter-block reduction). ──
    float p = 0.0f;
    #pragma unroll
    for (int j = 0; j < NJ; j++) {
        int k = krow + 128 * j;
        if (k < KTOT) p += sy[k] * breg[j];
    }
    #pragma unroll
    for (int off = 16; off > 0; off >>= 1)
        p += __shfl_down_sync(0xFFFFFFFFu, p, off);
    if (lane == 0) s_part[wid] = p;
    __syncthreads();
    if (tid < OPB) {                                  // one thread per output
        float r = s_part[4 * tid] + s_part[4 * tid + 1]
                + s_part[4 * tid + 2] + s_part[4 * tid + 3];
        out[blockIdx.x * OPB + tid] = r * inv;        // plain store
    }
    // no reset tail: g_arrive reset by releaser, g_rel monotonic,
    // slots invalidated by seq tag.
}

extern "C" void kernel_launch(void* const* d_in, const int* in_sizes, int n_in,
                              void* d_out, int out_size) {
    const float* ent    = (const float*)d_in[0];  // [100000, 200]
    const float* relemb = (const float*)d_in[1];  // [200, 200]
    const float* basis  = (const float*)d_in[2];  // [4, 400, 200]
    const float* att    = (const float*)d_in[3];  // [400, 4]
    const int* node_id  = (const int*)d_in[4];    // [50000]
    const int* edge_src = (const int*)d_in[5];    // [400000]
    const int* edge_dst = (const int*)d_in[6];    // [400000]
    const int* edge_typ = (const int*)d_in[7];    // [400000]
    const int* rel_idx  = (const int*)d_in[8];    // [400000]
    const int* u_ptr    = (const int*)d_in[9];    // scalar
    float* out = (float*)d_out;                   // [200]

    int E = in_sizes[6];

    fused_kernel<<<NBLK, NTHR>>>(ent, relemb, basis, att,
                                 node_id, edge_src, edge_dst, edge_typ, rel_idx,
                                 u_ptr, out, E);
}

// round 12
// speedup vs baseline: 2.2420x; 2.2420x over previous
#include <cuda_runtime.h>

// Problem constants (fixed by the reference setup)
#define DE   200          // entity / output dim
#define DR   200          // relation dim
#define DIN  400          // DE + DR
#define NB   4            // num bases
#define KTOT (NB * DIN)   // 1600 rows of the collapsed matvec

#define NBLK 148          // one wave
#define NTHR 512
#define NMM  37           // consumer (matvec) blocks: blockIdx 0..36
#define KCH  44           // k-rows per consumer block (37*44 = 1628 >= 1600)
#define KPG  22           // max k-rows per thread-group (2 groups x 256 thr)
#define MAXM 1024         // slot capacity (expected ~8 matches)
#define NSPEC 16          // slots processed speculatively (one per warp)

// persistent scratch (static device globals — no allocation).
// g_arrive: low16 = block arrivals, high16 = match count / slot allocator.
//           Reset to 0 by the releaser every launch.
// g_rel:    low32 = monotonically increasing launch sequence, high32 = count.
// g_slot:   bits[48:64) = launch seq tag (stale slots auto-invalid),
//           bits[18:35) = nid, [9:18) = ri, [0:9) = ty.
__device__ unsigned           g_arrive;
__device__ unsigned long long g_rel;
__device__ unsigned long long g_slot[MAXM];

__global__ void __launch_bounds__(NTHR, 1)
fused_kernel(const float* __restrict__ ent,
             const float* __restrict__ relemb,
             const float* __restrict__ basis,
             const float* __restrict__ att,
             const int*   __restrict__ node_id,
             const int*   __restrict__ edge_src,
             const int*   __restrict__ edge_dst,
             const int*   __restrict__ edge_type,
             const int*   __restrict__ rel_index,
             const int*   __restrict__ u_ptr,
             float* __restrict__ out,
             int E) {
    const int tid   = threadIdx.x;
    const bool is_mv = (blockIdx.x < NMM);

    __shared__ float sy[KCH];
    __shared__ float s1[256];
    __shared__ int   s_cnt;

    // Launch sequence: plain (L1-cached) load — one L2 touch per SM.
    const unsigned seq_old = (unsigned)__ldca(&g_rel);
    const unsigned seq16   = (seq_old + 1u) & 0xFFFFu;

    // block 0 zeroes the REDG target pre-barrier (barrier orders it
    // before every consumer's post-release REDG).
    if (blockIdx.x == 0 && tid < DE) out[tid] = 0.0f;

    // consumer blocks prefetch their basis chunk (overlaps the scan)
    const int k0   = blockIdx.x * KCH;
    const int kmax = is_mv ? ((KTOT - k0) < KCH ? (KTOT - k0) : KCH) : 0;
    const int g    = tid >> 8;       // 0 or 1
    const int o    = tid & 255;      // output index within group
    float breg[KPG];
    if (is_mv && o < DE) {
        #pragma unroll
        for (int j = 0; j < KPG; j++) {
            int kk = g * KPG + j;
            breg[j] = (kk < kmax) ? __ldcg(&basis[(size_t)(k0 + kk) * DE + o]) : 0.0f;
        }
    }
    if (tid < KCH) sy[tid] = 0.0f;
    __syncthreads();                 // sy visible before speculative adds

    // ── Phase 1: scan edge_dst (all 148 blocks). A finder allocates its slot
    //    from the SAME atomic counter the barrier uses (high16), resolves the
    //    pointer chain, and publishes ONE seq-tagged 64-bit word. ──
    auto found = [&](int e) {
        unsigned old = atomicAdd(&g_arrive, 1u << 16);
        unsigned p = old >> 16;
        if (p < MAXM) {
            int s  = __ldcg(&edge_src[e]);   // these three issue in parallel
            int ri = __ldcg(&rel_index[e]);
            int ty = __ldcg(&edge_type[e]);
            int nid = __ldcg(&node_id[s]);   // the only serial dependency
            *(volatile unsigned long long*)&g_slot[p] =
                  ((unsigned long long)seq16 << 48)
                | ((unsigned long long)(unsigned)nid << 18)
                | ((unsigned long long)(unsigned)ri  << 9)
                |  (unsigned long long)(unsigned)ty;
        }
    };
    {
        const int u  = *u_ptr;               // L1-cached broadcast
        const int gt = blockIdx.x * NTHR + tid;
        const int GT = NBLK * NTHR;
        const int nv = E >> 2;
        const int4* ed4 = (const int4*)edge_dst;
        for (int i = gt; i < nv; i += 2 * GT) {       // 2-wide MLP
            int  i2 = i + GT;
            bool h2 = i2 < nv;
            int4 v1 = __ldcg(&ed4[i]);
            int4 v2;
            if (h2) v2 = __ldcg(&ed4[i2]);
            int b1 = i << 2;
            if (v1.x == u) found(b1 + 0);
            if (v1.y == u) found(b1 + 1);
            if (v1.z == u) found(b1 + 2);
            if (v1.w == u) found(b1 + 3);
            if (h2) {
                int b2 = i2 << 2;
                if (v2.x == u) found(b2 + 0);
                if (v2.y == u) found(b2 + 1);
                if (v2.z == u) found(b2 + 2);
                if (v2.w == u) found(b2 + 3);
            }
        }
        for (int e = (nv << 2) + gt; e < E; e += GT) {  // scalar tail
            if (__ldcg(&edge_dst[e]) == u) found(e);
        }
    }

    // ── Barrier arrival. The releaser's OWN atomic return carries the final
    //    count (all finds precede all arrivals) — no extra count load. ──
    __syncthreads();
    if (tid == 0) {
        __threadfence();
        unsigned old = atomicAdd(&g_arrive, 1u);
        if ((old & 0xFFFFu) == NBLK - 1) {           // releaser
            unsigned cnt = old >> 16;
            g_arrive = 0;                             // reset for next launch
            __threadfence();
            atomicExch(&g_rel, ((unsigned long long)cnt << 32)
                               | (unsigned long long)(seq_old + 1u));
        }
    }

    if (!is_mv) return;                               // scan-only blocks done

    // ── Speculative consume (pre-release): warp w owns slot w. Poll the
    //    seq tag; process the instant it is published. Fall out when the
    //    release says this slot will never fill. ──
    {
        const int wid  = tid >> 5;
        const int lane = tid & 31;
        if (wid < NSPEC) {
            const int mm = wid;
            unsigned long long v;
            bool have = false;
            for (;;) {
                v = *(volatile unsigned long long*)&g_slot[mm];
                if ((unsigned)(v >> 48) == seq16) { have = true; break; }
                unsigned long long r = *(volatile unsigned long long*)&g_rel;
                if ((unsigned)r != seq_old) {         // released
                    int cnt = (int)(r >> 32);
                    if (mm >= cnt) break;             // never fills
                    __threadfence();                  // acquire
                    v = *(volatile unsigned long long*)&g_slot[mm];
                    have = ((unsigned)(v >> 48) == seq16);
                    break;
                }
            }
            if (have) {
                int nid = (int)((v >> 18) & 0x1FFFF);
                int ri  = (int)((v >> 9) & 0x1FF);
                int ty  = (int)(v & 0x1FF);
                const float* arow = att + (size_t)ty * NB;
                #pragma unroll
                for (int h = 0; h < 2; h++) {
                    int kk = lane + h * 32;
                    if (kk < kmax) {
                        int k = k0 + kk;
                        int b = k / DIN;
                        int i = k - b * DIN;
                        float x = (i < DE)
                            ? __ldcg(&ent[(size_t)nid * DE + i])
                            : __ldcg(&relemb[(size_t)ri * DR + (i - DE)]);
                        atomicAdd(&sy[kk], arow[b] * x);
                    }
                }
            }
        }
    }

    // ── Release wait (usually already satisfied) + rare tail for cnt>16 ──
    if (tid == 0) {
        unsigned long long r;
        do { r = *(volatile unsigned long long*)&g_rel; }
        while ((unsigned)r == seq_old);
        __threadfence();                              // acquire
        s_cnt = (int)(r >> 32);
    }
    __syncthreads();
    const int   cnt  = s_cnt;
    const int   cntc = cnt < MAXM ? cnt : MAXM;
    const float inv  = 1.0f / fmaxf((float)cnt, 1.0f);

    if (cntc > NSPEC) {                               // rare (expected cnt≈8)
        const int total = (cntc - NSPEC) * kmax;
        for (int p = tid; p < total; p += NTHR) {
            int mm = NSPEC + p / kmax;
            int kk = p - (mm - NSPEC) * kmax;
            unsigned long long v = g_slot[mm];
            int nid = (int)((v >> 18) & 0x1FFFF);
            int ri  = (int)((v >> 9) & 0x1FF);
            int ty  = (int)(v & 0x1FF);
            int k = k0 + kk;
            int b = k / DIN;
            int i = k - b * DIN;
            float x = (i < DE)
                ? __ldcg(&ent[(size_t)nid * DE + i])
                : __ldcg(&relemb[(size_t)ri * DR + (i - DE)]);
            atomicAdd(&sy[kk], att[ty * NB + b] * x);
        }
    }
    __syncthreads();                                  // sy complete

    // combine halves in smem -> ONE REDG lane per output element, pre-scaled
    float acc = 0.0f;
    if (o < DE) {
        #pragma unroll
        for (int j = 0; j < KPG; j++) {
            int kk = g * KPG + j;
            if (kk < kmax) acc += sy[kk] * breg[j];
        }
        if (g == 1) s1[o] = acc;
    }
    __syncthreads();
    if (o < DE && g == 0 && cntc > 0) {
        atomicAdd(&out[o], (acc + s1[o]) * inv);      // fire-and-forget REDG
    }
    // no reset tail: g_arrive reset by releaser, g_rel monotonic,
    // slots invalidated by seq tag.
}

extern "C" void kernel_launch(void* const* d_in, const int* in_sizes, int n_in,
                              void* d_out, int out_size) {
    const float* ent    = (const float*)d_in[0];  // [100000, 200]
    const float* relemb = (const float*)d_in[1];  // [200, 200]
    const float* basis  = (const float*)d_in[2];  // [4, 400, 200]
    const float* att    = (const float*)d_in[3];  // [400, 4]
    const int* node_id  = (const int*)d_in[4];    // [50000]
    const int* edge_src = (const int*)d_in[5];    // [400000]
    const int* edge_dst = (const int*)d_in[6];    // [400000]
    const int* edge_typ = (const int*)d_in[7];    // [400000]
    const int* rel_idx  = (const int*)d_in[8];    // [400000]
    const int* u_ptr    = (const int*)d_in[9];    // scalar
    float* out = (float*)d_out;                   // [200]

    int E = in_sizes[6];

    fused_kernel<<<NBLK, NTHR>>>(ent, relemb, basis, att,
                                 node_id, edge_src, edge_dst, edge_typ, rel_idx,
                                 u_ptr, out, E);
}

// round 13
// speedup vs baseline: 2.7464x; 1.2250x over previous
#include <cuda_runtime.h>

// Problem constants (fixed by the reference setup)
#define DE   200          // entity / output dim
#define DR   200          // relation dim
#define DIN  400          // DE + DR
#define NB   4            // num bases
#define KTOT (NB * DIN)   // 1600 rows of the collapsed matvec

#define NBLK 148          // one wave
#define NTHR 512          // 16 warps
#define NMM  37           // consumer blocks: blockIdx 0..36 (scan-free)
#define NSCAN (NBLK - NMM)      // 111 scan blocks: blockIdx 37..147
#define TARGET (NSCAN + 1)      // arrivals: 111 scan blocks + block 0 (out-zero)
#define KCH  44           // k-rows per consumer block (37*44 = 1628 >= 1600)
#define KPG  22           // k-rows per thread-group (2 groups x 256 threads)
#define MAXM 1024         // slot capacity (expected ~8 matches)
#define NSPEC 15          // spec warps 1..15 own slots 0..14

// persistent scratch (static device globals — no allocation).
// g_seq: monotonic launch counter (incremented once per launch by releaser).
// g_arr: double-buffered arrive/count word (low16 arrivals, high16 match
//        count). Buffer seq&1 is used this launch; the releaser zeroes the
//        OTHER buffer for the next launch. Padded to separate cache lines.
// g_slot: self-validating: bits[19:64) = seq+1 tag, bits[0:19) = edge index.
__device__ unsigned           g_seq;
__device__ unsigned           g_arr[2][32];
__device__ unsigned long long g_slot[MAXM];

__global__ void __launch_bounds__(NTHR, 1)
fused_kernel(const float* __restrict__ ent,
             const float* __restrict__ relemb,
             const float* __restrict__ basis,
             const float* __restrict__ att,
             const int*   __restrict__ node_id,
             const int*   __restrict__ edge_src,
             const int*   __restrict__ edge_dst,
             const int*   __restrict__ edge_type,
             const int*   __restrict__ rel_index,
             const int*   __restrict__ u_ptr,
             float* __restrict__ out,
             int E) {
    const int tid  = threadIdx.x;
    const int wid  = tid >> 5;
    const int lane = tid & 31;
    const bool is_mv = (blockIdx.x < NMM);

    const unsigned seq = g_seq;                        // stable this launch
    const unsigned par = seq & 1u;
    const unsigned long long tag = (unsigned long long)(seq + 1u);
    unsigned* arr      = &g_arr[par][0];
    unsigned* arr_next = &g_arr[par ^ 1u][0];

    // releaser duty: the TARGET-th arriver preps state for the next launch
    auto arrive = [&](void) {
        unsigned old = atomicAdd(arr, 1u);
        if ((old & 0xFFFFu) == TARGET - 1) {           // releaser
            *arr_next = 0;                             // next launch's buffer
            __threadfence();
            g_seq = seq + 1u;
        }
    };

    if (!is_mv) {
        // ───────────────────────── scan block ─────────────────────────
        // Finder publishes INSTANTLY: slot = (tag<<19)|e — no loads on the
        // finder path, so scan blocks arrive with zero straggler chain.
        auto found = [&](int e) {
            unsigned old = atomicAdd(arr, 1u << 16);
            unsigned p = old >> 16;
            if (p < MAXM)
                *(volatile unsigned long long*)&g_slot[p] =
                    (tag << 19) | (unsigned long long)(unsigned)e;
        };
        const int sgt = (blockIdx.x - NMM) * NTHR + tid;
        const int SGT = NSCAN * NTHR;
        const int u   = *u_ptr;                        // L1-cached broadcast
        const int nv  = E >> 2;
        const int4* ed4 = (const int4*)edge_dst;
        for (int i = sgt; i < nv; i += 2 * SGT) {      // 2-wide MLP, 1 iter
            int  i2 = i + SGT;
            bool h2 = i2 < nv;
            int4 v1 = __ldcg(&ed4[i]);
            int4 v2;
            if (h2) v2 = __ldcg(&ed4[i2]);
            int b1 = i << 2;
            if (v1.x == u) found(b1 + 0);
            if (v1.y == u) found(b1 + 1);
            if (v1.z == u) found(b1 + 2);
            if (v1.w == u) found(b1 + 3);
            if (h2) {
                int b2 = i2 << 2;
                if (v2.x == u) found(b2 + 0);
                if (v2.y == u) found(b2 + 1);
                if (v2.z == u) found(b2 + 2);
                if (v2.w == u) found(b2 + 3);
            }
        }
        for (int e = (nv << 2) + sgt; e < E; e += SGT) {   // scalar tail
            if (__ldcg(&edge_dst[e]) == u) found(e);
        }
        __syncthreads();
        if (tid == 0) { __threadfence(); arrive(); }
        return;                                        // scan blocks exit
    }

    // ──────────────────────── consumer block (no scan) ────────────────────
    const int k0   = blockIdx.x * KCH;
    const int kmax = (KTOT - k0) < KCH ? (KTOT - k0) : KCH;
    const int g    = tid >> 8;        // 0 or 1
    const int o    = tid & 255;       // output index within group

    __shared__ float        sy[KCH];
    __shared__ float        s1[256];
    __shared__ volatile int s_flag;
    __shared__ volatile int s_cnt;

    // block 0 zeroes the REDG target, then ARRIVES (so low16==TARGET orders
    // the zeroing before every consumer's REDG).
    if (blockIdx.x == 0) {
        if (tid < DE) out[tid] = 0.0f;
        __syncthreads();
        if (tid == 0) { __threadfence(); arrive(); }
    }

    // prefetch basis chunk into registers; zero sy and control flags
    float breg[KPG];
    if (o < DE) {
        #pragma unroll
        for (int j = 0; j < KPG; j++) {
            int kk = g * KPG + j;
            breg[j] = (kk < kmax) ? __ldcg(&basis[(size_t)(k0 + kk) * DE + o]) : 0.0f;
        }
    }
    if (tid < KCH) sy[tid] = 0.0f;
    if (tid == 0) { s_flag = 0; s_cnt = 0; }
    __syncthreads();

    // ── spec consume: warp w (1..15) polls slot w-1 from t=0; the meta chain
    //    (edge_src -> node_id -> x) runs DURING the scan. Warp 0/tid0 polls
    //    the arrive word and broadcasts completion via smem. ──
    if (wid == 0) {
        if (tid == 0) {
            unsigned v;
            do { v = *(volatile unsigned*)arr; } while ((v & 0xFFFFu) != TARGET);
            __threadfence();                           // acquire
            s_cnt = (int)(v >> 16);
            __threadfence_block();
            s_flag = 1;
        }
    } else {
        const int m = wid - 1;                         // slot owned by warp
        unsigned long long v;
        bool have = false;
        for (;;) {
            v = *(volatile unsigned long long*)&g_slot[m];
            if ((v >> 19) == tag) { have = true; break; }   // self-validating
            if (s_flag && s_cnt <= m) break;           // will never fill
        }
        if (have) {
            int e  = (int)(v & 0x7FFFFu);
            int s  = __ldcg(&edge_src[e]);             // these issue together
            int ri = __ldcg(&rel_index[e]);
            int ty = __ldcg(&edge_type[e]);
            int nid = __ldcg(&node_id[s]);             // serial hop
            const float* arow = att + (size_t)ty * NB;
            #pragma unroll
            for (int h = 0; h < 2; h++) {
                int kk = lane + h * 32;
                if (kk < kmax) {
                    int k = k0 + kk;
                    int b = k / DIN;
                    int i = k - b * DIN;
                    float x = (i < DE)
                        ? __ldcg(&ent[(size_t)nid * DE + i])
                        : __ldcg(&relemb[(size_t)ri * DR + (i - DE)]);
                    atomicAdd(&sy[kk], arow[b] * x);
                }
            }
        }
    }
    __syncthreads();

    const int   cnt  = s_cnt;
    const int   cntc = cnt < MAXM ? cnt : MAXM;
    const float inv  = 1.0f / fmaxf((float)cnt, 1.0f);

    if (cntc > NSPEC) {                                // rare (expected cnt≈8)
        const int total = (cntc - NSPEC) * kmax;
        for (int p = tid; p < total; p += NTHR) {
            int mm = NSPEC + p / kmax;
            int kk = p - (mm - NSPEC) * kmax;
            unsigned long long v = g_slot[mm];
            int e  = (int)(v & 0x7FFFFu);
            int s  = __ldcg(&edge_src[e]);
            int ri = __ldcg(&rel_index[e]);
            int ty = __ldcg(&edge_type[e]);
            int nid = __ldcg(&node_id[s]);
            int k = k0 + kk;
            int b = k / DIN;
            int i = k - b * DIN;
            float x = (i < DE)
                ? __ldcg(&ent[(size_t)nid * DE + i])
                : __ldcg(&relemb[(size_t)ri * DR + (i - DE)]);
            atomicAdd(&sy[kk], att[ty * NB + b] * x);
        }
        __syncthreads();
    }

    // combine halves in smem -> ONE REDG lane per output element, pre-scaled
    float acc = 0.0f;
    if (o < DE) {
        #pragma unroll
        for (int j = 0; j < KPG; j++) {
            int kk = g * KPG + j;
            if (kk < kmax) acc += sy[kk] * breg[j];
        }
        if (g == 1) s1[o] = acc;
    }
    __syncthreads();
    if (o < DE && g == 0 && cntc > 0) {
        atomicAdd(&out[o], (acc + s1[o]) * inv);       // fire-and-forget REDG
    }
    // no reset tail: arrive buffer for the next launch zeroed by the
    // releaser; g_seq monotonic; slots invalidated by the seq tag.
}

extern "C" void kernel_launch(void* const* d_in, const int* in_sizes, int n_in,
                              void* d_out, int out_size) {
    const float* ent    = (const float*)d_in[0];  // [100000, 200]
    const float* relemb = (const float*)d_in[1];  // [200, 200]
    const float* basis  = (const float*)d_in[2];  // [4, 400, 200]
    const float* att    = (const float*)d_in[3];  // [400, 4]
    const int* node_id  = (const int*)d_in[4];    // [50000]
    const int* edge_src = (const int*)d_in[5];    // [400000]
    const int* edge_dst = (const int*)d_in[6];    // [400000]
    const int* edge_typ = (const int*)d_in[7];    // [400000]
    const int* rel_idx  = (const int*)d_in[8];    // [400000]
    const int* u_ptr    = (const int*)d_in[9];    // scalar
    float* out = (float*)d_out;                   // [200]

    int E = in_sizes[6];

    fused_kernel<<<NBLK, NTHR>>>(ent, relemb, basis, att,
                                 node_id, edge_src, edge_dst, edge_typ, rel_idx,
                                 u_ptr, out, E);
}